// round 5
// baseline (speedup 1.0000x reference)
#include <cuda_runtime.h>
#include <cuda_bf16.h>

// GraphAggregation: out[b, :] = mean over 196 nodes of in[b].reshape(196, 4)
// Input : (B, 784) fp32. Row = 3136 B = 98 x 32B float8 chunks.
// Output: (B, 4) fp32.
//
// Persistent warps, one row per warp-iteration, grid-stride.
// Software-pipelined: next row's 256-bit loads are issued BEFORE the
// current row's reduction (which is what stalls on the scoreboard), so
// every warp keeps LDGs in flight continuously. Grid sized to exactly
// the resident block capacity (no partial-wave serialization).

#define N_NODES 196
#define ROW_FLOATS (N_NODES * 4)   // 784
#define DINV (1.0f / 196.0f)

// 256-bit load of 8 floats (sm_100+ LDG.E.256).
#define LDG256(r, ptr)                                                        \
    asm volatile("ld.global.nc.v8.f32 {%0,%1,%2,%3,%4,%5,%6,%7}, [%8];"       \
                 : "=f"((r)[0]), "=f"((r)[1]), "=f"((r)[2]), "=f"((r)[3]),    \
                   "=f"((r)[4]), "=f"((r)[5]), "=f"((r)[6]), "=f"((r)[7])     \
                 : "l"(ptr))

#define LOAD_ROW(r0, r1, r2, r3, base_ptr, lane)                              \
    do {                                                                      \
        const float* _p = (base_ptr) + (lane) * 8;                            \
        LDG256(r0, _p);          /* chunks  0..31 */                          \
        LDG256(r1, _p + 256);    /* chunks 32..63 */                          \
        LDG256(r2, _p + 512);    /* chunks 64..95 */                          \
        _Pragma("unroll")                                                     \
        for (int _i = 0; _i < 8; ++_i) (r3)[_i] = 0.f;                        \
        if ((lane) < 2) LDG256(r3, _p + 768);  /* chunks 96,97 */             \
    } while (0)

__global__ __launch_bounds__(256)
void graph_agg_kernel(const float* __restrict__ in, float4* __restrict__ out, int B)
{
    const int lane = threadIdx.x & 31;
    const int warp_id = (blockIdx.x * blockDim.x + threadIdx.x) >> 5;
    const int n_warps = (gridDim.x * blockDim.x) >> 5;

    float a0[8], a1[8], a2[8], a3[8];
    float b0[8], b1[8], b2[8], b3[8];

    int row = warp_id;
    if (row >= B) return;

    LOAD_ROW(a0, a1, a2, a3, in + (size_t)row * ROW_FLOATS, lane);

    while (row < B) {
        const int next = row + n_warps;

        // Prefetch next row BEFORE consuming current (keeps LDGs in flight
        // while the reduction below waits on the current row's scoreboard).
        if (next < B) {
            LOAD_ROW(b0, b1, b2, b3, in + (size_t)next * ROW_FLOATS, lane);
        }

        // Each float8 chunk = two node float4s: component d lives at
        // indices {d, d+4}.
        float sx = ((a0[0] + a0[4]) + (a1[0] + a1[4])) + ((a2[0] + a2[4]) + a3[0] + a3[4]);
        float sy = ((a0[1] + a0[5]) + (a1[1] + a1[5])) + ((a2[1] + a2[5]) + a3[1] + a3[5]);
        float sz = ((a0[2] + a0[6]) + (a1[2] + a1[6])) + ((a2[2] + a2[6]) + a3[2] + a3[6]);
        float sw = ((a0[3] + a0[7]) + (a1[3] + a1[7])) + ((a2[3] + a2[7]) + a3[3] + a3[7]);

        #pragma unroll
        for (int off = 16; off > 0; off >>= 1) {
            sx += __shfl_xor_sync(0xFFFFFFFFu, sx, off);
            sy += __shfl_xor_sync(0xFFFFFFFFu, sy, off);
            sz += __shfl_xor_sync(0xFFFFFFFFu, sz, off);
            sw += __shfl_xor_sync(0xFFFFFFFFu, sw, off);
        }

        if (lane == 0) {
            float4 r;
            r.x = sx * DINV;
            r.y = sy * DINV;
            r.z = sz * DINV;
            r.w = sw * DINV;
            out[row] = r;
        }

        // Rotate double buffer (values unused when next >= B).
        #pragma unroll
        for (int i = 0; i < 8; ++i) {
            a0[i] = b0[i]; a1[i] = b1[i]; a2[i] = b2[i]; a3[i] = b3[i];
        }
        row = next;
    }
}

extern "C" void kernel_launch(void* const* d_in, const int* in_sizes, int n_in,
                              void* d_out, int out_size)
{
    const float* in = (const float*)d_in[0];
    float4* out = (float4*)d_out;
    const int B = in_sizes[0] / ROW_FLOATS;      // 131072

    // Size the grid to exactly the resident capacity: persistent warps,
    // no serialized partial wave. (Host-side queries only; zero cost in
    // graph replay.)
    int dev = 0, sms = 0, max_blocks = 0;
    cudaGetDevice(&dev);
    cudaDeviceGetAttribute(&sms, cudaDevAttrMultiProcessorCount, dev);
    cudaOccupancyMaxActiveBlocksPerMultiprocessor(&max_blocks, graph_agg_kernel, 256, 0);
    if (sms <= 0) sms = 148;
    if (max_blocks <= 0) max_blocks = 3;

    int blocks = sms * max_blocks;
    int max_useful = (B + 7) / 8;                // one row per warp minimum
    if (blocks > max_useful) blocks = max_useful;

    graph_agg_kernel<<<blocks, 256>>>(in, out, B);
}

// round 6
// speedup vs baseline: 1.0275x; 1.0275x over previous
#include <cuda_runtime.h>
#include <cuda_bf16.h>

// GraphAggregation: out[b, :] = mean over 196 nodes of in[b].reshape(196, 4)
// Input : (B, 784) fp32. Output: (B, 4) fp32.
//
// One warp per TWO consecutive rows (6272 B = 196 x 32B float8 chunks).
// 6 unconditional 256-bit LDGs per lane + 1 predicated tail (lanes 0-3):
// front-batched MLP~7, fully coalesced 1KB warp-transactions.
// Row boundary at chunk 98 lands inside load k=3 only -> lane predicate
// at accumulate time. Two shuffle reductions, lane 0 writes both means.

#define N_NODES 196
#define ROW_FLOATS (N_NODES * 4)   // 784
#define DINV (1.0f / 196.0f)

// 256-bit load of 8 floats (sm_100+ LDG.E.256).
#define LDG256(r, ptr)                                                        \
    asm volatile("ld.global.nc.v8.f32 {%0,%1,%2,%3,%4,%5,%6,%7}, [%8];"       \
                 : "=f"((r)[0]), "=f"((r)[1]), "=f"((r)[2]), "=f"((r)[3]),    \
                   "=f"((r)[4]), "=f"((r)[5]), "=f"((r)[6]), "=f"((r)[7])     \
                 : "l"(ptr))

__global__ __launch_bounds__(256)
void graph_agg_kernel(const float* __restrict__ in, float4* __restrict__ out, int B)
{
    const int warp_in_block = threadIdx.x >> 5;
    const int lane = threadIdx.x & 31;
    const int pair = blockIdx.x * (blockDim.x >> 5) + warp_in_block;
    const int row0 = pair * 2;
    if (row0 >= B) return;

    // Two consecutive rows: chunks 0..195 (32B each). Lane t owns chunks
    // t, t+32, ..., t+192 (last predicated to lanes 0..3).
    const float* __restrict__ p = in + (size_t)row0 * ROW_FLOATS + lane * 8;

    float l0[8], l1[8], l2[8], l3[8], l4[8], l5[8];
    float l6[8] = {0.f, 0.f, 0.f, 0.f, 0.f, 0.f, 0.f, 0.f};

    LDG256(l0, p);             // chunks   0..31   row0
    LDG256(l1, p + 256);       // chunks  32..63   row0
    LDG256(l2, p + 512);       // chunks  64..95   row0
    LDG256(l3, p + 768);       // chunks  96..127  lanes 0,1 -> row0; 2.. -> row1
    LDG256(l4, p + 1024);      // chunks 128..159  row1
    LDG256(l5, p + 1280);      // chunks 160..191  row1
    if (lane < 4) {
        LDG256(l6, p + 1536);  // chunks 192..195  row1
    }

    // Per-thread partial 8-vectors for each row.
    float s0[8], s1[8];
    #pragma unroll
    for (int i = 0; i < 8; ++i) {
        s0[i] = (l0[i] + l1[i]) + l2[i];
        s1[i] = (l4[i] + l5[i]) + l6[i];
    }
    if (lane < 2) {
        #pragma unroll
        for (int i = 0; i < 8; ++i) s0[i] += l3[i];
    } else {
        #pragma unroll
        for (int i = 0; i < 8; ++i) s1[i] += l3[i];
    }

    // Collapse float8 -> 4-vector (components at {d, d+4}).
    float ax = s0[0] + s0[4], ay = s0[1] + s0[5], az = s0[2] + s0[6], aw = s0[3] + s0[7];
    float bx = s1[0] + s1[4], by = s1[1] + s1[5], bz = s1[2] + s1[6], bw = s1[3] + s1[7];

    #pragma unroll
    for (int off = 16; off > 0; off >>= 1) {
        ax += __shfl_xor_sync(0xFFFFFFFFu, ax, off);
        ay += __shfl_xor_sync(0xFFFFFFFFu, ay, off);
        az += __shfl_xor_sync(0xFFFFFFFFu, az, off);
        aw += __shfl_xor_sync(0xFFFFFFFFu, aw, off);
        bx += __shfl_xor_sync(0xFFFFFFFFu, bx, off);
        by += __shfl_xor_sync(0xFFFFFFFFu, by, off);
        bz += __shfl_xor_sync(0xFFFFFFFFu, bz, off);
        bw += __shfl_xor_sync(0xFFFFFFFFu, bw, off);
    }

    if (lane == 0) {
        float4 r0;
        r0.x = ax * DINV; r0.y = ay * DINV; r0.z = az * DINV; r0.w = aw * DINV;
        out[row0] = r0;
        if (row0 + 1 < B) {
            float4 r1;
            r1.x = bx * DINV; r1.y = by * DINV; r1.z = bz * DINV; r1.w = bw * DINV;
            out[row0 + 1] = r1;
        }
    }
}

extern "C" void kernel_launch(void* const* d_in, const int* in_sizes, int n_in,
                              void* d_out, int out_size)
{
    const float* in = (const float*)d_in[0];
    float4* out = (float4*)d_out;
    const int B = in_sizes[0] / ROW_FLOATS;      // 131072

    const int pairs = (B + 1) / 2;               // 65536 warps
    const int warps_per_block = 8;               // 256 threads
    const int blocks = (pairs + warps_per_block - 1) / warps_per_block;
    graph_agg_kernel<<<blocks, warps_per_block * 32>>>(in, out, B);
}